// round 2
// baseline (speedup 1.0000x reference)
#include <cuda_runtime.h>
#include <math.h>

#define NN 8192
#define FF 512
#define HH 64
#define NB 4096
#define C9 1.2340980408667956e-4f   /* expf(-9) */

// ---------------- scratch (static __device__, no allocations) ----------------
__device__ float g_fts[NN*HH];          // projected features [N,H]
__device__ float g_f1[NN];
__device__ float g_f2[NN];
__device__ float g_ef2[NN];             // exp(f2)
__device__ float g_lo;
__device__ float g_invw;
__device__ int   g_hist[NB];
__device__ int   g_bstart[NB+1];        // CSR offsets of buckets (also count-prefix)
__device__ int   g_fill[NB];
__device__ int   g_perm[NN];            // nodes grouped by bucket
__device__ float g_P0[(NB+1)*HH];       // P0[b][h] = sum_{buckets < b} fts   (P0[NB][h] = S[h])
__device__ float g_P1[(NB+1)*HH];       // P1[b][h] = sum_{buckets >= b} ef2*fts
__device__ float g_Db[NB+1];            // Db[b] = sum_{buckets >= b} ef2

// ---------------- K1: fts = features @ W  (fp32 tiled GEMM) ----------------
__global__ __launch_bounds__(256) void k_gemm(const float* __restrict__ A,
                                              const float* __restrict__ Wm) {
    __shared__ float As[16][68];   // transposed A tile [k][m], padded
    __shared__ float Bs[16][64];
    const int tid = threadIdx.x;
    const int m0 = blockIdx.x * 64;
    const int ty = tid >> 4, tx = tid & 15;
    const int arow = tid >> 2, akq = (tid & 3) * 4;
    const int brow = tid >> 4, bcol = (tid & 15) * 4;
    float acc[4][4];
#pragma unroll
    for (int i = 0; i < 4; i++)
#pragma unroll
        for (int j = 0; j < 4; j++) acc[i][j] = 0.f;

    for (int k0 = 0; k0 < FF; k0 += 16) {
        float4 av = *(const float4*)&A[(size_t)(m0 + arow) * FF + k0 + akq];
        float4 bv = *(const float4*)&Wm[(size_t)(k0 + brow) * HH + bcol];
        As[akq+0][arow] = av.x; As[akq+1][arow] = av.y;
        As[akq+2][arow] = av.z; As[akq+3][arow] = av.w;
        *(float4*)&Bs[brow][bcol] = bv;
        __syncthreads();
#pragma unroll
        for (int kk = 0; kk < 16; kk++) {
            float4 a4 = *(const float4*)&As[kk][ty * 4];
            float4 b4 = *(const float4*)&Bs[kk][tx * 4];
            float a[4] = {a4.x, a4.y, a4.z, a4.w};
            float b[4] = {b4.x, b4.y, b4.z, b4.w};
#pragma unroll
            for (int i = 0; i < 4; i++)
#pragma unroll
                for (int j = 0; j < 4; j++)
                    acc[i][j] = fmaf(a[i], b[j], acc[i][j]);
        }
        __syncthreads();
    }
#pragma unroll
    for (int i = 0; i < 4; i++) {
        float4 o = make_float4(acc[i][0], acc[i][1], acc[i][2], acc[i][3]);
        *(float4*)&g_fts[(size_t)(m0 + ty * 4 + i) * HH + tx * 4] = o;
    }
}

// ---------------- K2: f1, f2, ef2 (warp per row) ----------------
__global__ __launch_bounds__(256) void k_f12(const float* __restrict__ a1, const float* __restrict__ b1,
                                             const float* __restrict__ a2, const float* __restrict__ b2) {
    int gidx = blockIdx.x * 256 + threadIdx.x;
    int r = gidx >> 5;
    int lane = gidx & 31;
    if (r >= NN) return;
    float v0 = g_fts[r * HH + lane], v1 = g_fts[r * HH + lane + 32];
    float s1 = v0 * a1[lane] + v1 * a1[lane + 32];
    float s2 = v0 * a2[lane] + v1 * a2[lane + 32];
#pragma unroll
    for (int o = 16; o; o >>= 1) {
        s1 += __shfl_xor_sync(0xffffffffu, s1, o);
        s2 += __shfl_xor_sync(0xffffffffu, s2, o);
    }
    if (lane == 0) {
        float f1v = s1 + b1[0], f2v = s2 + b2[0];
        g_f1[r] = f1v; g_f2[r] = f2v; g_ef2[r] = __expf(f2v);
    }
}

// ---------------- K3: min/max of f2 + zero histogram ----------------
__global__ __launch_bounds__(1024) void k_minmax() {
    __shared__ float smin[1024], smax[1024];
    int tid = threadIdx.x;
    float lo = 3.4e38f, hi = -3.4e38f;
    for (int i = tid; i < NN; i += 1024) {
        float v = g_f2[i];
        lo = fminf(lo, v); hi = fmaxf(hi, v);
    }
    smin[tid] = lo; smax[tid] = hi; __syncthreads();
    for (int s = 512; s > 0; s >>= 1) {
        if (tid < s) {
            smin[tid] = fminf(smin[tid], smin[tid + s]);
            smax[tid] = fmaxf(smax[tid], smax[tid + s]);
        }
        __syncthreads();
    }
    if (tid == 0) {
        float l = smin[0], h = smax[0], w = h - l;
        g_lo = l;
        g_invw = (w > 0.f) ? (float)NB / w : 0.f;
    }
    for (int i = tid; i < NB; i += 1024) g_hist[i] = 0;
}

__device__ __forceinline__ int bucket_of(float v, float lo, float invw) {
    float x = (v - lo) * invw;
    int b = (int)x;
    if (b < 0) b = 0;
    if (b > NB - 1) b = NB - 1;
    return b;
}

// ---------------- K4: histogram ----------------
__global__ void k_hist() {
    int n = blockIdx.x * blockDim.x + threadIdx.x;
    if (n < NN) atomicAdd(&g_hist[bucket_of(g_f2[n], g_lo, g_invw)], 1);
}

// ---------------- K5: scan histogram -> CSR offsets ----------------
__global__ __launch_bounds__(1024) void k_scan() {
    __shared__ int s[1024];
    int tid = threadIdx.x;
    int4 hv = *(const int4*)&g_hist[tid * 4];
    int tot = hv.x + hv.y + hv.z + hv.w;
    s[tid] = tot; __syncthreads();
    for (int off = 1; off < 1024; off <<= 1) {
        int v = (tid >= off) ? s[tid - off] : 0;
        __syncthreads();
        s[tid] += v;
        __syncthreads();
    }
    int excl = (tid > 0) ? s[tid - 1] : 0;
    int b = tid * 4;
    g_bstart[b] = excl;   g_fill[b] = excl;   excl += hv.x;
    g_bstart[b+1] = excl; g_fill[b+1] = excl; excl += hv.y;
    g_bstart[b+2] = excl; g_fill[b+2] = excl; excl += hv.z;
    g_bstart[b+3] = excl; g_fill[b+3] = excl; excl += hv.w;
    if (tid == 1023) g_bstart[NB] = excl;
}

// ---------------- K6: scatter nodes into buckets ----------------
__global__ void k_scatter() {
    int n = blockIdx.x * blockDim.x + threadIdx.x;
    if (n < NN) {
        int b = bucket_of(g_f2[n], g_lo, g_invw);
        int pos = atomicAdd(&g_fill[b], 1);
        g_perm[pos] = n;
    }
}

// ---------------- K7: bucket prefix/suffix sums (block per h; block 64 = Db) ----------------
__global__ __launch_bounds__(256) void k_prescan() {
    const int hb = blockIdx.x;              // 0..63 -> h column; 64 -> Db
    const bool isDb = (hb == HH);
    const int tid = threadIdx.x;
    float s0[16], s1[16];
    const int b0 = tid * 16;
    float t0 = 0.f, t1 = 0.f;
#pragma unroll
    for (int u = 0; u < 16; u++) {
        int st = g_bstart[b0 + u], en = g_bstart[b0 + u + 1];
        float a0 = 0.f, a1v = 0.f;
        for (int i = st; i < en; i++) {
            int n = g_perm[i];
            float e = g_ef2[n];
            float f = isDb ? 1.f : g_fts[n * HH + hb];
            a0 += f; a1v += e * f;
        }
        s0[u] = a0; s1[u] = a1v; t0 += a0; t1 += a1v;
    }
    __shared__ float sh0[256], sh1[256];
    sh0[tid] = t0; sh1[tid] = t1; __syncthreads();
    for (int off = 1; off < 256; off <<= 1) {   // sh0: forward inclusive; sh1: backward inclusive
        float v0 = (tid >= off) ? sh0[tid - off] : 0.f;
        float v1 = (tid + off < 256) ? sh1[tid + off] : 0.f;
        __syncthreads();
        sh0[tid] += v0; sh1[tid] += v1;
        __syncthreads();
    }
    float run0 = (tid > 0)   ? sh0[tid - 1] : 0.f;  // exclusive prefix of thread totals
    float run1 = (tid < 255) ? sh1[tid + 1] : 0.f;  // exclusive suffix of thread totals
    if (!isDb) {
#pragma unroll
        for (int u = 0; u < 16; u++) { g_P0[(b0 + u) * HH + hb] = run0; run0 += s0[u]; }
        if (tid == 255) g_P0[NB * HH + hb] = run0;   // = S[h]
#pragma unroll
        for (int u = 15; u >= 0; u--) { run1 += s1[u]; g_P1[(b0 + u) * HH + hb] = run1; }
        if (tid == 0) g_P1[NB * HH + hb] = 0.f;
    } else {
#pragma unroll
        for (int u = 15; u >= 0; u--) { run1 += s1[u]; g_Db[b0 + u] = run1; }
        if (tid == 0) g_Db[NB] = 0.f;
    }
}

// ---------------- K8: fused per-row softmax + aggregation (block per row) ----------------
__global__ __launch_bounds__(256) void k_final(const float* __restrict__ bias,
                                               float* __restrict__ out) {
    const int m = blockIdx.x;
    const int tid = threadIdx.x;
    __shared__ int   sh_cols[1024];
    __shared__ float sh_w[1024];
    __shared__ float sE[256], sF[256], sZ[256];
    __shared__ int   sh_cnt;
    __shared__ float sh_Ze;
    if (tid == 0) sh_cnt = 0;
    __syncthreads();

    const float f1m = g_f1[m];
    // ---- Phase A: stream bias row once, collect edge columns (bias == 0) ----
    const float4* brow = (const float4*)(bias + (size_t)m * NN);
#pragma unroll
    for (int it = 0; it < 8; it++) {
        int i = tid + it * 256;
        float4 v = __ldg(&brow[i]);
        if (v.x == 0.f) { int p = atomicAdd(&sh_cnt, 1); if (p < 1024) sh_cols[p] = 4*i;   }
        if (v.y == 0.f) { int p = atomicAdd(&sh_cnt, 1); if (p < 1024) sh_cols[p] = 4*i+1; }
        if (v.z == 0.f) { int p = atomicAdd(&sh_cnt, 1); if (p < 1024) sh_cols[p] = 4*i+2; }
        if (v.w == 0.f) { int p = atomicAdd(&sh_cnt, 1); if (p < 1024) sh_cols[p] = 4*i+3; }
    }
    __syncthreads();
    int cnt = sh_cnt; if (cnt > 1024) cnt = 1024;

    // ---- Phase A2: edge weights + Ze partials ----
    float zep = 0.f;
    for (int j = tid; j < cnt; j += 256) {
        int n = sh_cols[j];
        float w = __expf(fmaxf(f1m + g_f2[n], 0.f));
        sh_w[j] = w; zep += w;
    }
    sZ[tid] = zep;
    __syncthreads();

    // ---- Phase B: edge aggregation, 4 groups x 64 h-lanes ----
    const int h = tid & 63, grp = tid >> 6;
    float eacc = 0.f, facc = 0.f;
    for (int j = grp; j < cnt; j += 4) {
        int n = sh_cols[j];
        float fv = g_fts[n * HH + h];
        eacc += sh_w[j] * fv;
        facc += fv;
    }
    sE[tid] = eacc; sF[tid] = facc;
    __syncthreads();
    if (tid < 128) sZ[tid] += sZ[tid + 128];
    __syncthreads();
    if (tid < 64)  sZ[tid] += sZ[tid + 64];
    __syncthreads();
    if (tid == 0) { float z = 0.f; for (int i = 0; i < 64; i++) z += sZ[i]; sh_Ze = z; }
    __syncthreads();

    if (tid < 64) {
        float E  = sE[tid] + sE[tid+64] + sE[tid+128] + sE[tid+192];
        float Fv = sF[tid] + sF[tid+64] + sF[tid+128] + sF[tid+192];
        float Ze = sh_Ze;
        // ---- dense part via bucket prefix sums ----
        float t = -f1m;
        float lo = g_lo, invw = g_invw;
        float x = (t - lo) * invw;
        int bq;
        if (x < 0.f) bq = -1;
        else { bq = (int)x; if (bq > NB - 1) bq = NB - 1; }

        float A = 0.f, Bv = 0.f, cntE = 0.f, dE = 0.f;
        if (bq >= 0) {
            int st = g_bstart[bq], en = g_bstart[bq + 1];
            for (int i = st; i < en; i++) {
                int n = g_perm[i];
                float f2n = g_f2[n];
                float fv = g_fts[n * HH + tid];
                if (f2n <= t) { A += fv; cntE += 1.f; }
                else { float e2 = g_ef2[n]; Bv += e2 * fv; dE += e2; }
            }
        }
        float P0v = (bq >= 0) ? g_P0[bq * HH + tid] : 0.f;
        float P1v = g_P1[(bq + 1) * HH + tid];
        float cb  = (bq >= 0) ? (float)g_bstart[bq] : 0.f;
        float Dbv = g_Db[bq + 1];
        float ef1 = __expf(f1m);

        float Dvec = (P0v + A) + ef1 * (P1v + Bv);     // sum_n exp(relu(f1+f2)) * fts
        float Zd   = (cb + cntE) + ef1 * (Dbv + dE);   // sum_n exp(relu(f1+f2))
        float num = C9 * Dvec + (1.f - C9) * E;
        float Zs  = C9 * Zd   + (1.f - C9) * Ze;
        float Sh  = g_P0[NB * HH + tid];               // column sum of fts
        float val = num / Zs - 9.f * (Sh - Fv);        // softmax@fts + bias@fts
        out[(size_t)m * HH + tid] = (val > 0.f) ? val : expm1f(val);
    }
}

// ---------------- launch ----------------
extern "C" void kernel_launch(void* const* d_in, const int* in_sizes, int n_in,
                              void* d_out, int out_size) {
    const float* features = (const float*)d_in[0];
    const float* bias_mat = (const float*)d_in[1];
    const float* Wm       = (const float*)d_in[2];
    const float* a1       = (const float*)d_in[3];
    const float* b1       = (const float*)d_in[4];
    const float* a2       = (const float*)d_in[5];
    const float* b2       = (const float*)d_in[6];
    float* out = (float*)d_out;

    k_gemm   <<<NN / 64, 256>>>(features, Wm);
    k_f12    <<<NN * 32 / 256, 256>>>(a1, b1, a2, b2);
    k_minmax <<<1, 1024>>>();
    k_hist   <<<NN / 256, 256>>>();
    k_scan   <<<1, 1024>>>();
    k_scatter<<<NN / 256, 256>>>();
    k_prescan<<<HH + 1, 256>>>();
    k_final  <<<NN, 256>>>(bias_mat, out);
}

// round 3
// speedup vs baseline: 1.0078x; 1.0078x over previous
#include <cuda_runtime.h>
#include <math.h>

#define NN 8192
#define FF 512
#define HH 64
#define NB 4096
#define C9 1.2340980408667956e-4f   /* expf(-9) */

// ---------------- scratch (static __device__, no allocations) ----------------
__device__ float g_fts[NN*HH];          // projected features [N,H]
__device__ float g_f1[NN];
__device__ float g_f2[NN];
__device__ float g_ef2[NN];             // exp(f2)
__device__ float g_lo;
__device__ float g_invw;
__device__ int   g_hist[NB];
__device__ int   g_bstart[NB+1];        // CSR offsets of buckets (also count-prefix)
__device__ int   g_fill[NB];
__device__ int   g_perm[NN];            // nodes grouped by bucket
__device__ float g_P0[(NB+1)*HH];       // P0[b][h] = sum_{buckets < b} fts   (P0[NB][h] = S[h])
__device__ float g_P1[(NB+1)*HH];       // P1[b][h] = sum_{buckets >= b} ef2*fts
__device__ float g_Db[NB+1];            // Db[b] = sum_{buckets >= b} ef2

// ---------------- K1: fts = features @ W  (fp32 tiled GEMM) ----------------
__global__ __launch_bounds__(256) void k_gemm(const float* __restrict__ A,
                                              const float* __restrict__ Wm) {
    __shared__ float As[16][68];   // transposed A tile [k][m], padded
    __shared__ float Bs[16][64];
    const int tid = threadIdx.x;
    const int m0 = blockIdx.x * 64;
    const int ty = tid >> 4, tx = tid & 15;
    const int arow = tid >> 2, akq = (tid & 3) * 4;
    const int brow = tid >> 4, bcol = (tid & 15) * 4;
    float acc[4][4];
#pragma unroll
    for (int i = 0; i < 4; i++)
#pragma unroll
        for (int j = 0; j < 4; j++) acc[i][j] = 0.f;

    for (int k0 = 0; k0 < FF; k0 += 16) {
        float4 av = *(const float4*)&A[(size_t)(m0 + arow) * FF + k0 + akq];
        float4 bv = *(const float4*)&Wm[(size_t)(k0 + brow) * HH + bcol];
        As[akq+0][arow] = av.x; As[akq+1][arow] = av.y;
        As[akq+2][arow] = av.z; As[akq+3][arow] = av.w;
        *(float4*)&Bs[brow][bcol] = bv;
        __syncthreads();
#pragma unroll
        for (int kk = 0; kk < 16; kk++) {
            float4 a4 = *(const float4*)&As[kk][ty * 4];
            float4 b4 = *(const float4*)&Bs[kk][tx * 4];
            float a[4] = {a4.x, a4.y, a4.z, a4.w};
            float b[4] = {b4.x, b4.y, b4.z, b4.w};
#pragma unroll
            for (int i = 0; i < 4; i++)
#pragma unroll
                for (int j = 0; j < 4; j++)
                    acc[i][j] = fmaf(a[i], b[j], acc[i][j]);
        }
        __syncthreads();
    }
#pragma unroll
    for (int i = 0; i < 4; i++) {
        float4 o = make_float4(acc[i][0], acc[i][1], acc[i][2], acc[i][3]);
        *(float4*)&g_fts[(size_t)(m0 + ty * 4 + i) * HH + tx * 4] = o;
    }
}

// ---------------- K2: f1, f2, ef2 (warp per row) ----------------
__global__ __launch_bounds__(256) void k_f12(const float* __restrict__ a1, const float* __restrict__ b1,
                                             const float* __restrict__ a2, const float* __restrict__ b2) {
    int gidx = blockIdx.x * 256 + threadIdx.x;
    int r = gidx >> 5;
    int lane = gidx & 31;
    if (r >= NN) return;
    float v0 = g_fts[r * HH + lane], v1 = g_fts[r * HH + lane + 32];
    float s1 = v0 * a1[lane] + v1 * a1[lane + 32];
    float s2 = v0 * a2[lane] + v1 * a2[lane + 32];
#pragma unroll
    for (int o = 16; o; o >>= 1) {
        s1 += __shfl_xor_sync(0xffffffffu, s1, o);
        s2 += __shfl_xor_sync(0xffffffffu, s2, o);
    }
    if (lane == 0) {
        float f1v = s1 + b1[0], f2v = s2 + b2[0];
        g_f1[r] = f1v; g_f2[r] = f2v; g_ef2[r] = __expf(f2v);
    }
}

// ---------------- K3: min/max of f2 + zero histogram ----------------
__global__ __launch_bounds__(1024) void k_minmax() {
    __shared__ float smin[1024], smax[1024];
    int tid = threadIdx.x;
    float lo = 3.4e38f, hi = -3.4e38f;
    for (int i = tid; i < NN; i += 1024) {
        float v = g_f2[i];
        lo = fminf(lo, v); hi = fmaxf(hi, v);
    }
    smin[tid] = lo; smax[tid] = hi; __syncthreads();
    for (int s = 512; s > 0; s >>= 1) {
        if (tid < s) {
            smin[tid] = fminf(smin[tid], smin[tid + s]);
            smax[tid] = fmaxf(smax[tid], smax[tid + s]);
        }
        __syncthreads();
    }
    if (tid == 0) {
        float l = smin[0], h = smax[0], w = h - l;
        g_lo = l;
        g_invw = (w > 0.f) ? (float)NB / w : 0.f;
    }
    for (int i = tid; i < NB; i += 1024) g_hist[i] = 0;
}

__device__ __forceinline__ int bucket_of(float v, float lo, float invw) {
    float x = (v - lo) * invw;
    int b = (int)x;
    if (b < 0) b = 0;
    if (b > NB - 1) b = NB - 1;
    return b;
}

// ---------------- K4: histogram ----------------
__global__ void k_hist() {
    int n = blockIdx.x * blockDim.x + threadIdx.x;
    if (n < NN) atomicAdd(&g_hist[bucket_of(g_f2[n], g_lo, g_invw)], 1);
}

// ---------------- K5: scan histogram -> CSR offsets ----------------
__global__ __launch_bounds__(1024) void k_scan() {
    __shared__ int s[1024];
    int tid = threadIdx.x;
    int4 hv = *(const int4*)&g_hist[tid * 4];
    int tot = hv.x + hv.y + hv.z + hv.w;
    s[tid] = tot; __syncthreads();
    for (int off = 1; off < 1024; off <<= 1) {
        int v = (tid >= off) ? s[tid - off] : 0;
        __syncthreads();
        s[tid] += v;
        __syncthreads();
    }
    int excl = (tid > 0) ? s[tid - 1] : 0;
    int b = tid * 4;
    g_bstart[b] = excl;   g_fill[b] = excl;   excl += hv.x;
    g_bstart[b+1] = excl; g_fill[b+1] = excl; excl += hv.y;
    g_bstart[b+2] = excl; g_fill[b+2] = excl; excl += hv.z;
    g_bstart[b+3] = excl; g_fill[b+3] = excl; excl += hv.w;
    if (tid == 1023) g_bstart[NB] = excl;
}

// ---------------- K6: scatter nodes into buckets ----------------
__global__ void k_scatter() {
    int n = blockIdx.x * blockDim.x + threadIdx.x;
    if (n < NN) {
        int b = bucket_of(g_f2[n], g_lo, g_invw);
        int pos = atomicAdd(&g_fill[b], 1);
        g_perm[pos] = n;
    }
}

// ---------------- K7: bucket prefix/suffix sums (block per h; block 64 = Db) ----------------
__global__ __launch_bounds__(256) void k_prescan() {
    const int hb = blockIdx.x;              // 0..63 -> h column; 64 -> Db
    const bool isDb = (hb == HH);
    const int tid = threadIdx.x;
    float s0[16], s1[16];
    const int b0 = tid * 16;
    float t0 = 0.f, t1 = 0.f;
#pragma unroll
    for (int u = 0; u < 16; u++) {
        int st = g_bstart[b0 + u], en = g_bstart[b0 + u + 1];
        float a0 = 0.f, a1v = 0.f;
        for (int i = st; i < en; i++) {
            int n = g_perm[i];
            float e = g_ef2[n];
            float f = isDb ? 1.f : g_fts[n * HH + hb];
            a0 += f; a1v += e * f;
        }
        s0[u] = a0; s1[u] = a1v; t0 += a0; t1 += a1v;
    }
    __shared__ float sh0[256], sh1[256];
    sh0[tid] = t0; sh1[tid] = t1; __syncthreads();
    for (int off = 1; off < 256; off <<= 1) {   // sh0: forward inclusive; sh1: backward inclusive
        float v0 = (tid >= off) ? sh0[tid - off] : 0.f;
        float v1 = (tid + off < 256) ? sh1[tid + off] : 0.f;
        __syncthreads();
        sh0[tid] += v0; sh1[tid] += v1;
        __syncthreads();
    }
    float run0 = (tid > 0)   ? sh0[tid - 1] : 0.f;  // exclusive prefix of thread totals
    float run1 = (tid < 255) ? sh1[tid + 1] : 0.f;  // exclusive suffix of thread totals
    if (!isDb) {
#pragma unroll
        for (int u = 0; u < 16; u++) { g_P0[(b0 + u) * HH + hb] = run0; run0 += s0[u]; }
        if (tid == 255) g_P0[NB * HH + hb] = run0;   // = S[h]
#pragma unroll
        for (int u = 15; u >= 0; u--) { run1 += s1[u]; g_P1[(b0 + u) * HH + hb] = run1; }
        if (tid == 0) g_P1[NB * HH + hb] = 0.f;
    } else {
#pragma unroll
        for (int u = 15; u >= 0; u--) { run1 += s1[u]; g_Db[b0 + u] = run1; }
        if (tid == 0) g_Db[NB] = 0.f;
    }
}

// ---------------- K8: fused per-row softmax + aggregation (block per row) ----------------
__global__ __launch_bounds__(256) void k_final(const float* __restrict__ bias,
                                               float* __restrict__ out) {
    const int m = blockIdx.x;
    const int tid = threadIdx.x;
    __shared__ int   sh_cols[1024];
    __shared__ float sh_w[1024];
    __shared__ float sE[256], sF[256], sZ[256];
    __shared__ int   sh_cnt;
    __shared__ float sh_Ze;
    if (tid == 0) sh_cnt = 0;
    __syncthreads();

    const float f1m = g_f1[m];
    // ---- Phase A: stream bias row once, collect edge columns (bias == 0) ----
    const float4* brow = (const float4*)(bias + (size_t)m * NN);
#pragma unroll
    for (int it = 0; it < 8; it++) {
        int i = tid + it * 256;
        float4 v = __ldg(&brow[i]);
        if (v.x == 0.f) { int p = atomicAdd(&sh_cnt, 1); if (p < 1024) sh_cols[p] = 4*i;   }
        if (v.y == 0.f) { int p = atomicAdd(&sh_cnt, 1); if (p < 1024) sh_cols[p] = 4*i+1; }
        if (v.z == 0.f) { int p = atomicAdd(&sh_cnt, 1); if (p < 1024) sh_cols[p] = 4*i+2; }
        if (v.w == 0.f) { int p = atomicAdd(&sh_cnt, 1); if (p < 1024) sh_cols[p] = 4*i+3; }
    }
    __syncthreads();
    int cnt = sh_cnt; if (cnt > 1024) cnt = 1024;

    // ---- Phase A2: edge weights + Ze partials ----
    float zep = 0.f;
    for (int j = tid; j < cnt; j += 256) {
        int n = sh_cols[j];
        float w = __expf(fmaxf(f1m + g_f2[n], 0.f));
        sh_w[j] = w; zep += w;
    }
    sZ[tid] = zep;
    __syncthreads();

    // ---- Phase B: edge aggregation, 4 groups x 64 h-lanes ----
    const int h = tid & 63, grp = tid >> 6;
    float eacc = 0.f, facc = 0.f;
    for (int j = grp; j < cnt; j += 4) {
        int n = sh_cols[j];
        float fv = g_fts[n * HH + h];
        eacc += sh_w[j] * fv;
        facc += fv;
    }
    sE[tid] = eacc; sF[tid] = facc;
    __syncthreads();
    if (tid < 128) sZ[tid] += sZ[tid + 128];
    __syncthreads();
    if (tid < 64)  sZ[tid] += sZ[tid + 64];
    __syncthreads();
    if (tid == 0) { float z = 0.f; for (int i = 0; i < 64; i++) z += sZ[i]; sh_Ze = z; }
    __syncthreads();

    if (tid < 64) {
        float E  = sE[tid] + sE[tid+64] + sE[tid+128] + sE[tid+192];
        float Fv = sF[tid] + sF[tid+64] + sF[tid+128] + sF[tid+192];
        float Ze = sh_Ze;
        // ---- dense part via bucket prefix sums ----
        float t = -f1m;
        float lo = g_lo, invw = g_invw;
        float x = (t - lo) * invw;
        int bq;
        if (x < 0.f) bq = -1;
        else { bq = (int)x; if (bq > NB - 1) bq = NB - 1; }

        float A = 0.f, Bv = 0.f, cntE = 0.f, dE = 0.f;
        if (bq >= 0) {
            int st = g_bstart[bq], en = g_bstart[bq + 1];
            for (int i = st; i < en; i++) {
                int n = g_perm[i];
                float f2n = g_f2[n];
                float fv = g_fts[n * HH + tid];
                if (f2n <= t) { A += fv; cntE += 1.f; }
                else { float e2 = g_ef2[n]; Bv += e2 * fv; dE += e2; }
            }
        }
        float P0v = (bq >= 0) ? g_P0[bq * HH + tid] : 0.f;
        float P1v = g_P1[(bq + 1) * HH + tid];
        float cb  = (bq >= 0) ? (float)g_bstart[bq] : 0.f;
        float Dbv = g_Db[bq + 1];
        float ef1 = __expf(f1m);

        float Dvec = (P0v + A) + ef1 * (P1v + Bv);     // sum_n exp(relu(f1+f2)) * fts
        float Zd   = (cb + cntE) + ef1 * (Dbv + dE);   // sum_n exp(relu(f1+f2))
        float num = C9 * Dvec + (1.f - C9) * E;
        float Zs  = C9 * Zd   + (1.f - C9) * Ze;
        float Sh  = g_P0[NB * HH + tid];               // column sum of fts
        float val = num / Zs - 9.f * (Sh - Fv);        // softmax@fts + bias@fts
        out[(size_t)m * HH + tid] = (val > 0.f) ? val : expm1f(val);
    }
}

// ---------------- launch ----------------
extern "C" void kernel_launch(void* const* d_in, const int* in_sizes, int n_in,
                              void* d_out, int out_size) {
    const float* features = (const float*)d_in[0];
    const float* bias_mat = (const float*)d_in[1];
    const float* Wm       = (const float*)d_in[2];
    const float* a1       = (const float*)d_in[3];
    const float* b1       = (const float*)d_in[4];
    const float* a2       = (const float*)d_in[5];
    const float* b2       = (const float*)d_in[6];
    float* out = (float*)d_out;

    k_gemm   <<<NN / 64, 256>>>(features, Wm);
    k_f12    <<<NN * 32 / 256, 256>>>(a1, b1, a2, b2);
    k_minmax <<<1, 1024>>>();
    k_hist   <<<NN / 256, 256>>>();
    k_scan   <<<1, 1024>>>();
    k_scatter<<<NN / 256, 256>>>();
    k_prescan<<<HH + 1, 256>>>();
    k_final  <<<NN, 256>>>(bias_mat, out);
}

// round 4
// speedup vs baseline: 1.1424x; 1.1335x over previous
#include <cuda_runtime.h>
#include <math.h>

#define NN 8192
#define FF 512
#define HH 64
#define NB 4096
#define MAXE 512
#define C9 1.2340980408667956e-4f   /* expf(-9) */

// ---------------- scratch (static __device__, no allocations) ----------------
__device__ float  g_fts[NN*HH];          // projected features [N,H]
__device__ float  g_f1[NN];
__device__ float2 g_f2e[NN];             // (f2, exp(f2))
__device__ float  g_lo;
__device__ float  g_invw;
__device__ int    g_bstart[NB+1];        // CSR offsets of buckets
__device__ int    g_perm[NN];            // nodes grouped by bucket
__device__ int    g_ecnt[NN];            // edges per row
__device__ int    g_ecols[(size_t)NN*MAXE]; // edge column lists (16MB)
__device__ float  g_P0[(NB+1)*HH];       // prefix:  sum_{buckets < b} fts   (P0[NB][h] = S[h])
__device__ float  g_P1[(NB+1)*HH];       // suffix:  sum_{buckets >= b} ef2*fts
__device__ float  g_Db[NB+1];            // suffix:  sum_{buckets >= b} ef2

// ---------------- K1: heterogeneous — GEMM (+f1/f2 epilogue) || edge extraction ----------------
__global__ __launch_bounds__(256) void k_mega(const float* __restrict__ A,
                                              const float* __restrict__ Wm,
                                              const float* __restrict__ bias,
                                              const float* __restrict__ a1, const float* __restrict__ b1,
                                              const float* __restrict__ a2, const float* __restrict__ b2) {
    const int tid = threadIdx.x;
    if (blockIdx.x < NN / 64) {
        // ======== GEMM path: fts = features @ W, tile 64x64 ========
        __shared__ float As[16][68];   // transposed A tile [k][m], padded
        __shared__ float Bs[16][64];
        const int m0 = blockIdx.x * 64;
        const int ty = tid >> 4, tx = tid & 15;
        const int arow = tid >> 2, akq = (tid & 3) * 4;
        const int brow = tid >> 4, bcol = (tid & 15) * 4;
        float acc[4][4];
#pragma unroll
        for (int i = 0; i < 4; i++)
#pragma unroll
            for (int j = 0; j < 4; j++) acc[i][j] = 0.f;

        for (int k0 = 0; k0 < FF; k0 += 16) {
            float4 av = *(const float4*)&A[(size_t)(m0 + arow) * FF + k0 + akq];
            float4 bv = *(const float4*)&Wm[(size_t)(k0 + brow) * HH + bcol];
            As[akq+0][arow] = av.x; As[akq+1][arow] = av.y;
            As[akq+2][arow] = av.z; As[akq+3][arow] = av.w;
            *(float4*)&Bs[brow][bcol] = bv;
            __syncthreads();
#pragma unroll
            for (int kk = 0; kk < 16; kk++) {
                float4 a4 = *(const float4*)&As[kk][ty * 4];
                float4 b4 = *(const float4*)&Bs[kk][tx * 4];
                float a[4] = {a4.x, a4.y, a4.z, a4.w};
                float b[4] = {b4.x, b4.y, b4.z, b4.w};
#pragma unroll
                for (int i = 0; i < 4; i++)
#pragma unroll
                    for (int j = 0; j < 4; j++)
                        acc[i][j] = fmaf(a[i], b[j], acc[i][j]);
            }
            __syncthreads();
        }
#pragma unroll
        for (int i = 0; i < 4; i++) {
            float4 o = make_float4(acc[i][0], acc[i][1], acc[i][2], acc[i][3]);
            *(float4*)&g_fts[(size_t)(m0 + ty * 4 + i) * HH + tx * 4] = o;
        }
        // ---- epilogue: f1/f2/ef2 straight from register accumulators ----
        float w1[4], w2[4];
#pragma unroll
        for (int j = 0; j < 4; j++) {
            int c = tx * 4 + j;
            w1[j] = __ldg(&a1[c]);
            w2[j] = __ldg(&a2[c]);
        }
        float s1[4], s2[4];
#pragma unroll
        for (int i = 0; i < 4; i++) {
            float t1 = 0.f, t2 = 0.f;
#pragma unroll
            for (int j = 0; j < 4; j++) {
                t1 = fmaf(acc[i][j], w1[j], t1);
                t2 = fmaf(acc[i][j], w2[j], t2);
            }
            s1[i] = t1; s2[i] = t2;
        }
        // reduce across the 16 tx lanes (aligned 16-lane groups within the warp)
#pragma unroll
        for (int o = 1; o < 16; o <<= 1) {
#pragma unroll
            for (int i = 0; i < 4; i++) {
                s1[i] += __shfl_xor_sync(0xffffffffu, s1[i], o);
                s2[i] += __shfl_xor_sync(0xffffffffu, s2[i], o);
            }
        }
        if (tx == 0) {
            float bb1 = __ldg(&b1[0]), bb2 = __ldg(&b2[0]);
#pragma unroll
            for (int i = 0; i < 4; i++) {
                int r = m0 + ty * 4 + i;
                float f1v = s1[i] + bb1, f2v = s2[i] + bb2;
                g_f1[r] = f1v;
                g_f2e[r] = make_float2(f2v, __expf(f2v));
            }
        }
    } else {
        // ======== edge-extraction path: one block per bias row ========
        const int m = blockIdx.x - NN / 64;
        __shared__ int sh_cols[MAXE];
        __shared__ int sh_cnt;
        if (tid == 0) sh_cnt = 0;
        __syncthreads();
        const float4* brow = (const float4*)(bias + (size_t)m * NN);
        float4 v[8];
#pragma unroll
        for (int it = 0; it < 8; it++) v[it] = __ldg(&brow[tid + it * 256]);  // MLP=8
#pragma unroll
        for (int it = 0; it < 8; it++) {
            int i = tid + it * 256;
            if (v[it].x == 0.f) { int p = atomicAdd(&sh_cnt, 1); if (p < MAXE) sh_cols[p] = 4*i;   }
            if (v[it].y == 0.f) { int p = atomicAdd(&sh_cnt, 1); if (p < MAXE) sh_cols[p] = 4*i+1; }
            if (v[it].z == 0.f) { int p = atomicAdd(&sh_cnt, 1); if (p < MAXE) sh_cols[p] = 4*i+2; }
            if (v[it].w == 0.f) { int p = atomicAdd(&sh_cnt, 1); if (p < MAXE) sh_cols[p] = 4*i+3; }
        }
        __syncthreads();
        int cnt = sh_cnt; if (cnt > MAXE) cnt = MAXE;
        for (int j = tid; j < cnt; j += 256) g_ecols[(size_t)m * MAXE + j] = sh_cols[j];
        if (tid == 0) g_ecnt[m] = cnt;
    }
}

__device__ __forceinline__ int bucket_of(float v, float lo, float invw) {
    float x = (v - lo) * invw;
    int b = (int)x;
    if (b < 0) b = 0;
    if (b > NB - 1) b = NB - 1;
    return b;
}

// ---------------- K2: fused minmax + histogram + scan + scatter (single block) ----------------
__global__ __launch_bounds__(1024) void k_prep() {
    __shared__ float sred[1024];
    __shared__ int   hist[NB];      // 16KB, doubles as fill counters after scan
    __shared__ int   wsum[1024];
    const int tid = threadIdx.x;

    float f2v[8];
    float lo = 3.4e38f, hi = -3.4e38f;
#pragma unroll
    for (int it = 0; it < 8; it++) {
        float v = g_f2e[tid + it * 1024].x;
        f2v[it] = v;
        lo = fminf(lo, v); hi = fmaxf(hi, v);
    }
    sred[tid] = lo; __syncthreads();
    for (int s = 512; s > 0; s >>= 1) { if (tid < s) sred[tid] = fminf(sred[tid], sred[tid+s]); __syncthreads(); }
    const float LO = sred[0]; __syncthreads();
    sred[tid] = hi; __syncthreads();
    for (int s = 512; s > 0; s >>= 1) { if (tid < s) sred[tid] = fmaxf(sred[tid], sred[tid+s]); __syncthreads(); }
    const float HI = sred[0];
    const float w = HI - LO;
    const float INVW = (w > 0.f) ? (float)NB / w : 0.f;
    if (tid == 0) { g_lo = LO; g_invw = INVW; }

    for (int i = tid; i < NB; i += 1024) hist[i] = 0;
    __syncthreads();
    int bks[8];
#pragma unroll
    for (int it = 0; it < 8; it++) {
        bks[it] = bucket_of(f2v[it], LO, INVW);
        atomicAdd(&hist[bks[it]], 1);
    }
    __syncthreads();
    // scan: 4 buckets per thread
    int h4[4];
#pragma unroll
    for (int u = 0; u < 4; u++) h4[u] = hist[tid * 4 + u];
    int tot = h4[0] + h4[1] + h4[2] + h4[3];
    wsum[tid] = tot; __syncthreads();
    for (int off = 1; off < 1024; off <<= 1) {
        int v = (tid >= off) ? wsum[tid - off] : 0;
        __syncthreads();
        wsum[tid] += v;
        __syncthreads();
    }
    int excl = (tid > 0) ? wsum[tid - 1] : 0;
#pragma unroll
    for (int u = 0; u < 4; u++) {
        int b = tid * 4 + u;
        g_bstart[b] = excl;
        hist[b] = excl;          // becomes fill counter
        excl += h4[u];
    }
    if (tid == 1023) g_bstart[NB] = excl;
    __syncthreads();
    // scatter
#pragma unroll
    for (int it = 0; it < 8; it++) {
        int n = tid + it * 1024;
        int pos = atomicAdd(&hist[bks[it]], 1);
        g_perm[pos] = n;
    }
}

// ---------------- K3: bucket prefix/suffix sums (block per h; block 64 = Db) ----------------
__global__ __launch_bounds__(256) void k_prescan() {
    const int hb = blockIdx.x;              // 0..63 -> h column; 64 -> Db
    const bool isDb = (hb == HH);
    const int tid = threadIdx.x;
    float s0[16], s1[16];
    const int b0 = tid * 16;
    float t0 = 0.f, t1 = 0.f;
#pragma unroll
    for (int u = 0; u < 16; u++) {
        int st = g_bstart[b0 + u], en = g_bstart[b0 + u + 1];
        float a0 = 0.f, a1v = 0.f;
        for (int i = st; i < en; i++) {
            int n = g_perm[i];
            float e = g_f2e[n].y;
            float f = isDb ? 1.f : g_fts[n * HH + hb];
            a0 += f; a1v += e * f;
        }
        s0[u] = a0; s1[u] = a1v; t0 += a0; t1 += a1v;
    }
    __shared__ float sh0[256], sh1[256];
    sh0[tid] = t0; sh1[tid] = t1; __syncthreads();
    for (int off = 1; off < 256; off <<= 1) {   // sh0: forward inclusive; sh1: backward inclusive
        float v0 = (tid >= off) ? sh0[tid - off] : 0.f;
        float v1 = (tid + off < 256) ? sh1[tid + off] : 0.f;
        __syncthreads();
        sh0[tid] += v0; sh1[tid] += v1;
        __syncthreads();
    }
    float run0 = (tid > 0)   ? sh0[tid - 1] : 0.f;
    float run1 = (tid < 255) ? sh1[tid + 1] : 0.f;
    if (!isDb) {
#pragma unroll
        for (int u = 0; u < 16; u++) { g_P0[(b0 + u) * HH + hb] = run0; run0 += s0[u]; }
        if (tid == 255) g_P0[NB * HH + hb] = run0;   // = S[h]
#pragma unroll
        for (int u = 15; u >= 0; u--) { run1 += s1[u]; g_P1[(b0 + u) * HH + hb] = run1; }
        if (tid == 0) g_P1[NB * HH + hb] = 0.f;
    } else {
#pragma unroll
        for (int u = 15; u >= 0; u--) { run1 += s1[u]; g_Db[b0 + u] = run1; }
        if (tid == 0) g_Db[NB] = 0.f;
    }
}

// ---------------- K4: per-row softmax + aggregation from edge lists (block per row) ----------------
__global__ __launch_bounds__(256) void k_final(float* __restrict__ out) {
    const int m = blockIdx.x;
    const int tid = threadIdx.x;
    __shared__ int   sh_cols[MAXE];
    __shared__ float sh_w[MAXE];
    __shared__ float sE[256], sF[256], sZ[256];
    __shared__ float sh_Ze;

    const int cnt = g_ecnt[m];
    const float f1m = g_f1[m];
    const float ef1 = __expf(f1m);

    // load edge list, compute weights + Ze partials
    float zep = 0.f;
    for (int j = tid; j < cnt; j += 256) {
        int n = __ldg(&g_ecols[(size_t)m * MAXE + j]);
        sh_cols[j] = n;
        float2 fe = g_f2e[n];
        float w = (f1m + fe.x <= 0.f) ? 1.f : ef1 * fe.y;
        sh_w[j] = w; zep += w;
    }
    sZ[tid] = zep;
    __syncthreads();

    // edge aggregation: 4 groups x 64 h-lanes
    const int h = tid & 63, grp = tid >> 6;
    float eacc = 0.f, facc = 0.f;
    for (int j = grp; j < cnt; j += 4) {
        int n = sh_cols[j];
        float fv = g_fts[n * HH + h];
        eacc = fmaf(sh_w[j], fv, eacc);
        facc += fv;
    }
    sE[tid] = eacc; sF[tid] = facc;
    __syncthreads();
    if (tid < 128) sZ[tid] += sZ[tid + 128];
    __syncthreads();
    if (tid < 64)  sZ[tid] += sZ[tid + 64];
    __syncthreads();
    if (tid < 32) {
        float z = sZ[tid] + sZ[tid + 32];
#pragma unroll
        for (int o = 16; o; o >>= 1) z += __shfl_xor_sync(0xffffffffu, z, o);
        if (tid == 0) sh_Ze = z;
    }
    __syncthreads();

    if (tid < 64) {
        float E  = sE[tid] + sE[tid+64] + sE[tid+128] + sE[tid+192];
        float Fv = sF[tid] + sF[tid+64] + sF[tid+128] + sF[tid+192];
        float Ze = sh_Ze;
        // ---- dense part via bucket prefix sums ----
        float t = -f1m;
        float x = (t - g_lo) * g_invw;
        int bq;
        if (x < 0.f) bq = -1;
        else { bq = (int)x; if (bq > NB - 1) bq = NB - 1; }

        float A = 0.f, Bv = 0.f, cntE = 0.f, dE = 0.f;
        if (bq >= 0) {
            int st = g_bstart[bq], en = g_bstart[bq + 1];
            for (int i = st; i < en; i++) {
                int n = g_perm[i];
                float2 fe = g_f2e[n];
                float fv = g_fts[n * HH + tid];
                if (fe.x <= t) { A += fv; cntE += 1.f; }
                else { Bv = fmaf(fe.y, fv, Bv); dE += fe.y; }
            }
        }
        float P0v = (bq >= 0) ? g_P0[bq * HH + tid] : 0.f;
        float P1v = g_P1[(bq + 1) * HH + tid];
        float cb  = (bq >= 0) ? (float)g_bstart[bq] : 0.f;
        float Dbv = g_Db[bq + 1];

        float Dvec = (P0v + A) + ef1 * (P1v + Bv);     // sum_n exp(relu(f1+f2)) * fts
        float Zd   = (cb + cntE) + ef1 * (Dbv + dE);   // sum_n exp(relu(f1+f2))
        float num = C9 * Dvec + (1.f - C9) * E;
        float Zs  = C9 * Zd   + (1.f - C9) * Ze;
        float Sh  = g_P0[NB * HH + tid];               // column sum of fts
        float val = num / Zs - 9.f * (Sh - Fv);        // softmax@fts + bias@fts
        out[(size_t)m * HH + tid] = (val > 0.f) ? val : expm1f(val);
    }
}

// ---------------- launch ----------------
extern "C" void kernel_launch(void* const* d_in, const int* in_sizes, int n_in,
                              void* d_out, int out_size) {
    const float* features = (const float*)d_in[0];
    const float* bias_mat = (const float*)d_in[1];
    const float* Wm       = (const float*)d_in[2];
    const float* a1       = (const float*)d_in[3];
    const float* b1       = (const float*)d_in[4];
    const float* a2       = (const float*)d_in[5];
    const float* b2       = (const float*)d_in[6];
    float* out = (float*)d_out;

    k_mega   <<<NN / 64 + NN, 256>>>(features, Wm, bias_mat, a1, b1, a2, b2);
    k_prep   <<<1, 1024>>>();
    k_prescan<<<HH + 1, 256>>>();
    k_final  <<<NN, 256>>>(out);
}